// round 2
// baseline (speedup 1.0000x reference)
#include <cuda_runtime.h>

typedef unsigned long long u64;

#define D_ 128
#define K_ 8
#define TILE_ROWS 64
#define NTHREADS 256
#define W_STRIDE 132   // padded row stride for transposed W (16B-aligned, conflict-light staging)

// smem layout (floats):
//  Wt:     128*132            = 16896
//  xdup:   2 * 64*128*2 (u64) = 32768 floats
//  b,g,be: 3*128              = 384
//  cb:     8*128              = 1024
//  cbinv:  8
#define SMEM_FLOATS (16896 + 32768 + 384 + 1024 + 8)

__device__ __forceinline__ u64 ffma2(u64 a, u64 b, u64 c) {
    u64 d;
    asm("fma.rn.f32x2 %0, %1, %2, %3;" : "=l"(d) : "l"(a), "l"(b), "l"(c));
    return d;
}

__device__ __forceinline__ float2 u2f(u64 v) {
    float2 f;
    asm("mov.b64 {%0, %1}, %2;" : "=f"(f.x), "=f"(f.y) : "l"(v));
    return f;
}

__global__ __launch_bounds__(NTHREADS, 1)
void l1q_kernel(const float* __restrict__ x,
                const float* __restrict__ W,
                const float* __restrict__ bias,
                const float* __restrict__ gamma,
                const float* __restrict__ beta,
                const float* __restrict__ cb,
                float* __restrict__ o_idx,
                float* __restrict__ o_soft,
                float* __restrict__ o_emb,
                float* __restrict__ o_log,
                int B, int NT)
{
    extern __shared__ float sm[];
    float* Wt    = sm;                         // [128][W_STRIDE]
    u64*   xd0   = (u64*)(sm + 16896);         // [64][128] dup pairs
    u64*   xd1   = xd0 + 64 * 128;
    float* sb    = sm + 16896 + 32768;         // 128
    float* sg    = sb + 128;
    float* sbe   = sg + 128;
    float* scb   = sbe + 128;                  // 8*128 raw codebook
    float* scinv = scb + 1024;                 // 8

    const int tid = threadIdx.x;

    // ---- one-time staging: W (transposed), params, codebook ----
    #pragma unroll 4
    for (int i = tid; i < D_ * D_; i += NTHREADS) {
        int j = i >> 7, d = i & 127;
        Wt[d * W_STRIDE + j] = W[i];           // W[j][d] -> Wt[d][j]
    }
    if (tid < D_) { sb[tid] = bias[tid]; sg[tid] = gamma[tid]; sbe[tid] = beta[tid]; }
    for (int i = tid; i < K_ * D_; i += NTHREADS) scb[i] = cb[i];
    __syncthreads();
    if (tid < K_) {
        float s = 0.f;
        #pragma unroll
        for (int d = 0; d < D_; d++) { float v = scb[tid * D_ + d]; s += v * v; }
        scinv[tid] = 1.0f / fmaxf(sqrtf(s), 1e-12f);
    }

    const int cx = tid & 15;        // 16 lanes cover 128 cols (8 each)
    const int ry = tid >> 4;        // 16 row groups x 4 rows = 64-row tile
    const int jbase = cx * 8;

    float4 stg[8];

    auto LOADT = [&](int tt) {
        const float4* src = (const float4*)(x + (size_t)tt * TILE_ROWS * D_);
        #pragma unroll
        for (int kq = 0; kq < 8; kq++) {
            int q = tid + kq * NTHREADS;                 // float4 index in tile
            int row = tt * TILE_ROWS + (q >> 5);
            stg[kq] = (row < B) ? src[q] : make_float4(0.f, 0.f, 0.f, 0.f);
        }
    };
    auto STORET = [&](u64* buf) {
        float4* dst = (float4*)buf;
        #pragma unroll
        for (int kq = 0; kq < 8; kq++) {
            int q = tid + kq * NTHREADS;
            dst[q * 2 + 0] = make_float4(stg[kq].x, stg[kq].x, stg[kq].y, stg[kq].y);
            dst[q * 2 + 1] = make_float4(stg[kq].z, stg[kq].z, stg[kq].w, stg[kq].w);
        }
    };

    int t = blockIdx.x;
    if (t < NT) { LOADT(t); STORET(xd0); }
    __syncthreads();
    int pb = 0;

    const float inv128 = 1.0f / 128.0f;

    for (; t < NT; t += gridDim.x) {
        int tn = t + gridDim.x;
        if (tn < NT) LOADT(tn);                 // prefetch next tile into regs

        // ---- GEMM: 4 rows x 8 cols per thread, f32x2 packed FMA ----
        u64 acc[4][4];
        #pragma unroll
        for (int r = 0; r < 4; r++)
            #pragma unroll
            for (int p = 0; p < 4; p++) acc[r][p] = 0ull;   // (0.f,0.f)

        const u64* xb = (pb ? xd1 : xd0) + (ry * 4) * D_;

        #pragma unroll 4
        for (int d = 0; d < D_; d += 2) {
            ulonglong2 wA01 = *(const ulonglong2*)&Wt[d * W_STRIDE + jbase];
            ulonglong2 wA23 = *(const ulonglong2*)&Wt[d * W_STRIDE + jbase + 4];
            ulonglong2 wB01 = *(const ulonglong2*)&Wt[(d + 1) * W_STRIDE + jbase];
            ulonglong2 wB23 = *(const ulonglong2*)&Wt[(d + 1) * W_STRIDE + jbase + 4];
            #pragma unroll
            for (int r = 0; r < 4; r++) {
                ulonglong2 xp = *(const ulonglong2*)&xb[r * D_ + d];  // (x_d,x_d),(x_d1,x_d1)
                acc[r][0] = ffma2(xp.x, wA01.x, acc[r][0]);
                acc[r][1] = ffma2(xp.x, wA01.y, acc[r][1]);
                acc[r][2] = ffma2(xp.x, wA23.x, acc[r][2]);
                acc[r][3] = ffma2(xp.x, wA23.y, acc[r][3]);
                acc[r][0] = ffma2(xp.y, wB01.x, acc[r][0]);
                acc[r][1] = ffma2(xp.y, wB01.y, acc[r][1]);
                acc[r][2] = ffma2(xp.y, wB23.x, acc[r][2]);
                acc[r][3] = ffma2(xp.y, wB23.y, acc[r][3]);
            }
        }

        // ---- epilogue: LN -> l2norm -> logits -> softmax/argmax -> writes ----
        int rowbase = t * TILE_ROWS + ry * 4;
        #pragma unroll
        for (int r = 0; r < 4; r++) {
            int row = rowbase + r;
            float h[8];
            #pragma unroll
            for (int p = 0; p < 4; p++) {
                float2 f = u2f(acc[r][p]);
                h[2 * p]     = f.x + sb[jbase + 2 * p];
                h[2 * p + 1] = f.y + sb[jbase + 2 * p + 1];
            }
            float s1 = 0.f, s2 = 0.f;
            #pragma unroll
            for (int j = 0; j < 8; j++) { s1 += h[j]; s2 += h[j] * h[j]; }
            #pragma unroll
            for (int m = 1; m <= 8; m <<= 1) {
                s1 += __shfl_xor_sync(0xffffffffu, s1, m);
                s2 += __shfl_xor_sync(0xffffffffu, s2, m);
            }
            float mu   = s1 * inv128;
            float var  = s2 * inv128 - mu * mu;
            float rstd = rsqrtf(var + 1e-5f);

            float hn[8]; float q2 = 0.f;
            #pragma unroll
            for (int j = 0; j < 8; j++) {
                hn[j] = (h[j] - mu) * rstd * sg[jbase + j] + sbe[jbase + j];
                q2 += hn[j] * hn[j];
            }
            #pragma unroll
            for (int m = 1; m <= 8; m <<= 1) q2 += __shfl_xor_sync(0xffffffffu, q2, m);
            float invn = 1.0f / fmaxf(sqrtf(q2), 1e-12f);

            float lg[8];
            #pragma unroll
            for (int k = 0; k < K_; k++) {
                const float4* c = (const float4*)&scb[k * D_ + jbase];
                float4 c0 = c[0], c1 = c[1];
                float a = hn[0] * c0.x + hn[1] * c0.y + hn[2] * c0.z + hn[3] * c0.w
                        + hn[4] * c1.x + hn[5] * c1.y + hn[6] * c1.z + hn[7] * c1.w;
                #pragma unroll
                for (int m = 1; m <= 8; m <<= 1) a += __shfl_xor_sync(0xffffffffu, a, m);
                lg[k] = a * invn * scinv[k];
            }

            float mx = lg[0]; int bi = 0;
            #pragma unroll
            for (int k = 1; k < K_; k++) if (lg[k] > mx) { mx = lg[k]; bi = k; }
            float e[8], ssum = 0.f;
            #pragma unroll
            for (int k = 0; k < K_; k++) { e[k] = __expf(lg[k] - mx); ssum += e[k]; }
            float rs = 1.0f / ssum;

            if (row < B) {
                const float4* cr = (const float4*)&scb[bi * D_ + jbase];
                float4 e0 = cr[0], e1 = cr[1];
                float4* dst = (float4*)&o_emb[(size_t)row * D_ + jbase];
                dst[0] = e0; dst[1] = e1;
                if (cx == 0) {
                    o_idx[row] = (float)bi;
                    *(float4*)&o_soft[(size_t)row * 8]     = make_float4(e[0]*rs, e[1]*rs, e[2]*rs, e[3]*rs);
                    *(float4*)&o_soft[(size_t)row * 8 + 4] = make_float4(e[4]*rs, e[5]*rs, e[6]*rs, e[7]*rs);
                    *(float4*)&o_log [(size_t)row * 8]     = make_float4(lg[0], lg[1], lg[2], lg[3]);
                    *(float4*)&o_log [(size_t)row * 8 + 4] = make_float4(lg[4], lg[5], lg[6], lg[7]);
                }
            }
        }

        if (tn < NT) STORET(pb ? xd0 : xd1);
        __syncthreads();
        pb ^= 1;
    }
}

extern "C" void kernel_launch(void* const* d_in, const int* in_sizes, int n_in,
                              void* d_out, int out_size) {
    const float* x  = (const float*)d_in[0];
    const float* W  = (const float*)d_in[1];
    const float* b  = (const float*)d_in[2];
    const float* g  = (const float*)d_in[3];
    const float* be = (const float*)d_in[4];
    const float* cb = (const float*)d_in[5];

    int B = in_sizes[0] / D_;
    float* out    = (float*)d_out;
    float* o_idx  = out;
    float* o_soft = out + (size_t)B;
    float* o_emb  = o_soft + (size_t)B * K_;
    float* o_log  = o_emb + (size_t)B * D_;

    int NT = (B + TILE_ROWS - 1) / TILE_ROWS;
    int sms = 148;
    cudaDeviceGetAttribute(&sms, cudaDevAttrMultiProcessorCount, 0);
    int grid = (NT < sms) ? NT : sms;

    size_t smem = (size_t)SMEM_FLOATS * sizeof(float);
    cudaFuncSetAttribute(l1q_kernel, cudaFuncAttributeMaxDynamicSharedMemorySize, (int)smem);
    l1q_kernel<<<grid, NTHREADS, smem>>>(x, W, b, g, be, cb,
                                         o_idx, o_soft, o_emb, o_log, B, NT);
}

// round 8
// speedup vs baseline: 2.0715x; 2.0715x over previous
#include <cuda_runtime.h>
#include <cuda_fp16.h>
#include <cstdint>

#define D_ 128
#define TM 128
#define NTH 128
#define XSCALE 1024.0f
#define WSCALE 256.0f
#define INV_SC 3.814697265625e-06f   // 2^-18

// smem layout (bytes)
#define WB 36992                      // 136 n-rows * 272 (136 halves, padded stride)
#define OFF_W1 0
#define OFF_W2 WB
#define OFF_X  (2*WB)                 // 73984
#define XB 67584                      // 128 rows * 528 (132 floats padded)
#define OFF_SB  (OFF_X + 2*XB)        // 209152
#define OFF_SG  (OFF_SB + 512)
#define OFF_SBE (OFF_SG + 512)
#define OFF_SCB (OFF_SBE + 512)       // 8 * 132 * 4 = 4224
#define OFF_GK  (OFF_SCB + 4224)
#define OFF_BBK (OFF_GK + 32)
#define OFF_BDK (OFF_BBK + 32)
#define OFF_SCI (OFF_BDK + 32)
#define OFF_SBI (OFF_SCI + 32)
#define SMEM_TOTAL (OFF_SBI + 512)

__device__ __forceinline__ uint32_t s2u(const void* p) {
    uint32_t a;
    asm("{ .reg .u64 t; cvta.to.shared.u64 t, %1; cvt.u32.u64 %0, t; }" : "=r"(a) : "l"(p));
    return a;
}
__device__ __forceinline__ uint32_t f2h2(float lo, float hi) {
    uint32_t d;
    asm("cvt.rn.f16x2.f32 %0, %1, %2;" : "=r"(d) : "f"(hi), "f"(lo));
    return d;
}
__device__ __forceinline__ float2 h2f2(uint32_t h) {
    float2 r;
    asm("{ .reg .b16 l, hh; mov.b32 {l, hh}, %2; cvt.f32.f16 %0, l; cvt.f32.f16 %1, hh; }"
        : "=f"(r.x), "=f"(r.y) : "r"(h));
    return r;
}
__device__ __forceinline__ void split2(float a, float b, uint32_t& hi, uint32_t& lo) {
    hi = f2h2(a, b);
    float2 f = h2f2(hi);
    lo = f2h2(a - f.x, b - f.y);
}
__device__ __forceinline__ void ldmx2(uint32_t& r0, uint32_t& r1, uint32_t addr) {
    asm volatile("ldmatrix.sync.aligned.m8n8.x2.shared.b16 {%0,%1}, [%2];"
                 : "=r"(r0), "=r"(r1) : "r"(addr));
}
__device__ __forceinline__ void mma16816(float4& c, uint32_t a0, uint32_t a1, uint32_t a2, uint32_t a3,
                                         uint32_t b0, uint32_t b1) {
    asm volatile("mma.sync.aligned.m16n8k16.row.col.f32.f16.f16.f32 "
                 "{%0,%1,%2,%3},{%4,%5,%6,%7},{%8,%9},{%0,%1,%2,%3};"
                 : "+f"(c.x), "+f"(c.y), "+f"(c.z), "+f"(c.w)
                 : "r"(a0), "r"(a1), "r"(a2), "r"(a3), "r"(b0), "r"(b1));
}
__device__ __forceinline__ void cpasync16(uint32_t s, const void* g) {
    asm volatile("cp.async.cg.shared.global [%0], [%1], 16;" :: "r"(s), "l"(g));
}

__global__ void __launch_bounds__(NTH, 1)
l1q_mma(const float* __restrict__ x, const float* __restrict__ W,
        const float* __restrict__ bias, const float* __restrict__ gamma,
        const float* __restrict__ beta, const float* __restrict__ cb,
        float* __restrict__ o_idx, float* __restrict__ o_soft,
        float* __restrict__ o_emb, float* __restrict__ o_log,
        int B, int NT, int grid)
{
    extern __shared__ char sm[];
    const uint32_t base = s2u(sm);
    const int tid = threadIdx.x;
    const int lane = tid & 31;
    const int warp = tid >> 5;

    // ---- issue tile-0 cp.async immediately (overlaps with staging) ----
    int t0 = blockIdx.x;
    auto issue_tile = [&](int t, int buf) {
        uint32_t xb = base + OFF_X + (uint32_t)buf * XB;
        const char* src = (const char*)(x + (size_t)t * (TM * D_));
        #pragma unroll
        for (int i = 0; i < 32; i++) {
            int q = tid + i * NTH;
            int row = q >> 5, c4 = q & 31;
            const char* g = ((t * TM + row) < B) ? (src + (size_t)q * 16) : (const char*)x;
            cpasync16(xb + (uint32_t)row * 528 + (uint32_t)c4 * 16, g);
        }
        asm volatile("cp.async.commit_group;" ::: "memory");
    };
    if (t0 < NT) issue_tile(t0, 0);

    float* sb  = (float*)(sm + OFF_SB);
    float* sg  = (float*)(sm + OFF_SG);
    float* sbe = (float*)(sm + OFF_SBE);
    float* scb = (float*)(sm + OFF_SCB);
    float* gk  = (float*)(sm + OFF_GK);
    float* bbk = (float*)(sm + OFF_BBK);
    float* bdk = (float*)(sm + OFF_BDK);
    float* sci = (float*)(sm + OFF_SCI);
    int*   sbi = (int*)(sm + OFF_SBI);

    // ---- stage W (scaled x256, fp16 hi/lo split) as [n][k], stride 136 halves ----
    #pragma unroll 1
    for (int q2 = tid; q2 < 8192; q2 += NTH) {
        int n = q2 >> 6, kp = q2 & 63;
        float2 v = *(const float2*)&W[(size_t)n * 128 + 2 * kp];
        v.x *= WSCALE; v.y *= WSCALE;
        uint32_t hi, lo; split2(v.x, v.y, hi, lo);
        uint32_t off = (uint32_t)n * 272 + (uint32_t)kp * 4;
        *(uint32_t*)(sm + OFF_W1 + off) = hi;
        *(uint32_t*)(sm + OFF_W2 + off) = lo;
    }
    sb[tid] = bias[tid]; sg[tid] = gamma[tid]; sbe[tid] = beta[tid];
    #pragma unroll 1
    for (int i = tid; i < 1024; i += NTH) { int k = i >> 7, j = i & 127; scb[k * 132 + j] = cb[i]; }
    __syncthreads();

    // ---- ck'' = W^T (gamma o c_k) appended as B-rows 128..135 ----
    {
        int d = tid;
        float a8[8] = {0, 0, 0, 0, 0, 0, 0, 0};
        #pragma unroll 4
        for (int j = 0; j < 128; j++) {
            float tj = W[(size_t)j * 128 + d] * sg[j];
            #pragma unroll
            for (int k = 0; k < 8; k++) a8[k] = fmaf(tj, scb[k * 132 + j], a8[k]);
        }
        #pragma unroll
        for (int k = 0; k < 8; k++) {
            float vs = a8[k] * WSCALE;
            __half h1 = __float2half_rn(vs);
            __half h2 = __float2half_rn(vs - __half2float(h1));
            uint32_t off = (uint32_t)(128 + k) * 272 + (uint32_t)d * 2;
            *(__half*)(sm + OFF_W1 + off) = h1;
            *(__half*)(sm + OFF_W2 + off) = h2;
        }
    }
    if (tid < 8) {
        int k = tid; float g = 0, bb = 0, bd = 0, s2 = 0;
        for (int j = 0; j < 128; j++) {
            float c = scb[k * 132 + j], gj = sg[j];
            g  = fmaf(gj, c, g);
            bb = fmaf(sbe[j], c, bb);
            bd = fmaf(sb[j] * gj, c, bd);
            s2 = fmaf(c, c, s2);
        }
        gk[k] = g; bbk[k] = bb; bdk[k] = bd;
        sci[k] = 1.0f / fmaxf(sqrtf(s2), 1e-12f);
    }
    __syncthreads();

    const int g4 = lane >> 2, c4l = lane & 3;
    const int lr = lane & 15;
    const uint32_t wrow = (uint32_t)(lr & 7) * 272 + ((lr >> 3) ? 16u : 0u);

    int s = 0;
    for (int t = t0; t < NT; t += grid) {
        int tn = t + grid;
        bool more = (tn < NT);
        if (more) {
            issue_tile(tn, s ^ 1);
            asm volatile("cp.async.wait_group 1;" ::: "memory");
        } else {
            asm volatile("cp.async.wait_group 0;" ::: "memory");
        }
        __syncthreads();

        // ---- MMA: 4 warps x 32 rows, N=136 (17 n-tiles), K=128, 3 passes ----
        float4 acc[2][17];
        #pragma unroll
        for (int st = 0; st < 2; st++)
            #pragma unroll
            for (int j = 0; j < 17; j++) acc[st][j] = make_float4(0.f, 0.f, 0.f, 0.f);

        const char* smx = sm + OFF_X + (size_t)s * XB;
        const uint32_t xrow0 = (uint32_t)(warp * 32 + g4) * 528;

        #pragma unroll 1
        for (int ks = 0; ks < 8; ks++) {
            uint32_t ah[2][4], al[2][4];
            #pragma unroll
            for (int st = 0; st < 2; st++) {
                const char* p = smx + xrow0 + (uint32_t)st * (16 * 528) + (uint32_t)(ks * 16 + 2 * c4l) * 4;
                float2 v0 = *(const float2*)(p);
                float2 v1 = *(const float2*)(p + 8 * 528);
                float2 v2 = *(const float2*)(p + 32);
                float2 v3 = *(const float2*)(p + 8 * 528 + 32);
                split2(v0.x * XSCALE, v0.y * XSCALE, ah[st][0], al[st][0]);
                split2(v1.x * XSCALE, v1.y * XSCALE, ah[st][1], al[st][1]);
                split2(v2.x * XSCALE, v2.y * XSCALE, ah[st][2], al[st][2]);
                split2(v3.x * XSCALE, v3.y * XSCALE, ah[st][3], al[st][3]);
            }
            uint32_t wk = base + wrow + (uint32_t)ks * 32;
            #pragma unroll
            for (int j = 0; j < 17; j++) {
                uint32_t waddr = wk + (uint32_t)j * (8 * 272);
                uint32_t bh0, bh1, bl0, bl1;
                ldmx2(bh0, bh1, waddr + OFF_W1);
                ldmx2(bl0, bl1, waddr + OFF_W2);
                mma16816(acc[0][j], ah[0][0], ah[0][1], ah[0][2], ah[0][3], bh0, bh1);
                mma16816(acc[1][j], ah[1][0], ah[1][1], ah[1][2], ah[1][3], bh0, bh1);
                mma16816(acc[0][j], ah[0][0], ah[0][1], ah[0][2], ah[0][3], bl0, bl1);
                mma16816(acc[1][j], ah[1][0], ah[1][1], ah[1][2], ah[1][3], bl0, bl1);
                mma16816(acc[0][j], al[0][0], al[0][1], al[0][2], al[0][3], bh0, bh1);
                mma16816(acc[1][j], al[1][0], al[1][1], al[1][2], al[1][3], bh0, bh1);
            }
        }

        // ---- epilogue: 4 rows per thread-quad slot ----
        #pragma unroll
        for (int rp = 0; rp < 4; rp++) {
            int st = rp >> 1, hf = rp & 1;
            int rowloc = warp * 32 + st * 16 + hf * 8 + g4;
            int grow = t * TM + rowloc;

            float s1 = 0.f, s2 = 0.f;
            #pragma unroll
            for (int j = 0; j < 16; j++) {
                float a0 = hf ? acc[st][j].z : acc[st][j].x;
                float a1 = hf ? acc[st][j].w : acc[st][j].y;
                float2 bb = *(const float2*)(sm + OFF_SB + (8 * j + 2 * c4l) * 4);
                float h0 = fmaf(a0, INV_SC, bb.x);
                float h1 = fmaf(a1, INV_SC, bb.y);
                s1 += h0 + h1;
                s2 = fmaf(h0, h0, fmaf(h1, h1, s2));
            }
            s1 += __shfl_xor_sync(0xffffffffu, s1, 1);
            s1 += __shfl_xor_sync(0xffffffffu, s1, 2);
            s2 += __shfl_xor_sync(0xffffffffu, s2, 1);
            s2 += __shfl_xor_sync(0xffffffffu, s2, 2);
            float mu = s1 * 0.0078125f;
            float var = s2 * 0.0078125f - mu * mu;
            float rstd = rsqrtf(var + 1e-5f);

            float q2 = 0.f;
            #pragma unroll
            for (int j = 0; j < 16; j++) {
                float a0 = hf ? acc[st][j].z : acc[st][j].x;
                float a1 = hf ? acc[st][j].w : acc[st][j].y;
                float2 bb = *(const float2*)(sm + OFF_SB + (8 * j + 2 * c4l) * 4);
                float2 gg = *(const float2*)(sm + OFF_SG + (8 * j + 2 * c4l) * 4);
                float2 be = *(const float2*)(sm + OFF_SBE + (8 * j + 2 * c4l) * 4);
                float h0 = fmaf(a0, INV_SC, bb.x);
                float h1 = fmaf(a1, INV_SC, bb.y);
                float hn0 = fmaf((h0 - mu) * rstd, gg.x, be.x);
                float hn1 = fmaf((h1 - mu) * rstd, gg.y, be.y);
                q2 = fmaf(hn0, hn0, fmaf(hn1, hn1, q2));
            }
            q2 += __shfl_xor_sync(0xffffffffu, q2, 1);
            q2 += __shfl_xor_sync(0xffffffffu, q2, 2);
            float invn = 1.0f / fmaxf(sqrtf(q2), 1e-12f);

            float k0 = hf ? acc[st][16].z : acc[st][16].x;
            float k1 = hf ? acc[st][16].w : acc[st][16].y;
            float H0 = fmaf(k0, INV_SC, bdk[2 * c4l]);
            float H1 = fmaf(k1, INV_SC, bdk[2 * c4l + 1]);
            float l0 = fmaf(rstd, H0 - mu * gk[2 * c4l],     bbk[2 * c4l])     * invn * sci[2 * c4l];
            float l1 = fmaf(rstd, H1 - mu * gk[2 * c4l + 1], bbk[2 * c4l + 1]) * invn * sci[2 * c4l + 1];

            float lg[8];
            #pragma unroll
            for (int kk = 0; kk < 8; kk++) {
                int src = (lane & ~3) | (kk >> 1);
                lg[kk] = __shfl_sync(0xffffffffu, (kk & 1) ? l1 : l0, src);
            }
            float mx = lg[0]; int bi = 0;
            #pragma unroll
            for (int kk = 1; kk < 8; kk++) if (lg[kk] > mx) { mx = lg[kk]; bi = kk; }
            float e[8], ss = 0.f;
            #pragma unroll
            for (int kk = 0; kk < 8; kk++) { e[kk] = __expf(lg[kk] - mx); ss += e[kk]; }
            float rs = 1.0f / ss;

            if (c4l == 0) {
                sbi[rowloc] = bi;
                if (grow < B) {
                    o_idx[grow] = (float)bi;
                    *(float4*)&o_soft[(size_t)grow * 8]     = make_float4(e[0]*rs, e[1]*rs, e[2]*rs, e[3]*rs);
                    *(float4*)&o_soft[(size_t)grow * 8 + 4] = make_float4(e[4]*rs, e[5]*rs, e[6]*rs, e[7]*rs);
                    *(float4*)&o_log [(size_t)grow * 8]     = make_float4(lg[0], lg[1], lg[2], lg[3]);
                    *(float4*)&o_log [(size_t)grow * 8 + 4] = make_float4(lg[4], lg[5], lg[6], lg[7]);
                }
            }
        }
        __syncthreads();

        // ---- embedding write (coalesced) ----
        #pragma unroll
        for (int i = 0; i < 32; i++) {
            int q = tid + i * NTH;
            int r = q >> 5, c4 = q & 31;
            int grow = t * TM + r;
            if (grow < B) {
                float4 v = *(const float4*)(sm + OFF_SCB + ((size_t)sbi[r] * 132 + c4 * 4) * 4);
                *(float4*)&o_emb[(size_t)grow * 128 + c4 * 4] = v;
            }
        }
        __syncthreads();
        s ^= 1;
    }
}

extern "C" void kernel_launch(void* const* d_in, const int* in_sizes, int n_in,
                              void* d_out, int out_size) {
    const float* x  = (const float*)d_in[0];
    const float* W  = (const float*)d_in[1];
    const float* b  = (const float*)d_in[2];
    const float* g  = (const float*)d_in[3];
    const float* be = (const float*)d_in[4];
    const float* cb = (const float*)d_in[5];

    int B = in_sizes[0] / D_;
    float* out    = (float*)d_out;
    float* o_idx  = out;
    float* o_soft = out + (size_t)B;
    float* o_emb  = o_soft + (size_t)B * 8;
    float* o_log  = o_emb + (size_t)B * 128;

    int NT = (B + TM - 1) / TM;
    int sms = 148;
    cudaDeviceGetAttribute(&sms, cudaDevAttrMultiProcessorCount, 0);
    int grid = (NT < sms) ? NT : sms;

    cudaFuncSetAttribute(l1q_mma, cudaFuncAttributeMaxDynamicSharedMemorySize, SMEM_TOTAL);
    l1q_mma<<<grid, NTH, SMEM_TOTAL>>>(x, W, b, g, be, cb,
                                       o_idx, o_soft, o_emb, o_log, B, NT, grid);
}

// round 10
// speedup vs baseline: 2.8555x; 1.3785x over previous
#include <cuda_runtime.h>
#include <cuda_fp16.h>
#include <cstdint>

#define D_ 128
#define TM 128
#define NTH 256
#define XSCALE 1024.0f
#define WSCALE 256.0f
#define INV_SC 3.814697265625e-06f   // 2^-18

// smem layout (bytes)
#define WB 36992                      // 136 n-rows * 272 B (136 halves, padded stride)
#define OFF_W1 0
#define OFF_W2 WB
#define OFF_X  (2*WB)                 // 73984
#define XB 67584                      // 128 rows * 528 B (132 floats padded)
#define OFF_SB  (OFF_X + 2*XB)        // 209152
#define OFF_SG  (OFF_SB + 512)
#define OFF_SBE (OFF_SG + 512)
#define OFF_SCB (OFF_SBE + 512)       // 8 * 132 * 4 = 4224
#define OFF_GK  (OFF_SCB + 4224)
#define OFF_BBK (OFF_GK + 32)
#define OFF_BDK (OFF_BBK + 32)
#define OFF_SCI (OFF_BDK + 32)
#define SMEM_TOTAL (OFF_SCI + 32)

__device__ __forceinline__ uint32_t s2u(const void* p) {
    uint32_t a;
    asm("{ .reg .u64 t; cvta.to.shared.u64 t, %1; cvt.u32.u64 %0, t; }" : "=r"(a) : "l"(p));
    return a;
}
__device__ __forceinline__ uint32_t f2h2(float lo, float hi) {
    uint32_t d;
    asm("cvt.rn.f16x2.f32 %0, %1, %2;" : "=r"(d) : "f"(hi), "f"(lo));
    return d;
}
__device__ __forceinline__ float2 h2f2(uint32_t h) {
    float2 r;
    asm("{ .reg .b16 l, hh; mov.b32 {l, hh}, %2; cvt.f32.f16 %0, l; cvt.f32.f16 %1, hh; }"
        : "=f"(r.x), "=f"(r.y) : "r"(h));
    return r;
}
__device__ __forceinline__ void split2(float a, float b, uint32_t& hi, uint32_t& lo) {
    hi = f2h2(a, b);
    float2 f = h2f2(hi);
    lo = f2h2(a - f.x, b - f.y);
}
__device__ __forceinline__ void ldmx4(uint32_t* r, uint32_t addr) {
    asm volatile("ldmatrix.sync.aligned.m8n8.x4.shared.b16 {%0,%1,%2,%3}, [%4];"
                 : "=r"(r[0]), "=r"(r[1]), "=r"(r[2]), "=r"(r[3]) : "r"(addr));
}
__device__ __forceinline__ void mma16816(float4& c, const uint32_t* a, uint32_t b0, uint32_t b1) {
    asm volatile("mma.sync.aligned.m16n8k16.row.col.f32.f16.f16.f32 "
                 "{%0,%1,%2,%3},{%4,%5,%6,%7},{%8,%9},{%0,%1,%2,%3};"
                 : "+f"(c.x), "+f"(c.y), "+f"(c.z), "+f"(c.w)
                 : "r"(a[0]), "r"(a[1]), "r"(a[2]), "r"(a[3]), "r"(b0), "r"(b1));
}
__device__ __forceinline__ void cpasync16(uint32_t s, const void* g) {
    asm volatile("cp.async.cg.shared.global [%0], [%1], 16;" :: "r"(s), "l"(g));
}

__global__ void __launch_bounds__(NTH, 1)
l1q_mma(const float* __restrict__ x, const float* __restrict__ W,
        const float* __restrict__ bias, const float* __restrict__ gamma,
        const float* __restrict__ beta, const float* __restrict__ cb,
        float* __restrict__ o_idx, float* __restrict__ o_soft,
        float* __restrict__ o_emb, float* __restrict__ o_log,
        int B, int NT, int grid)
{
    extern __shared__ char sm[];
    const uint32_t base = s2u(sm);
    const int tid = threadIdx.x;
    const int lane = tid & 31;
    const int warp = tid >> 5;

    // ---- per-warp tile loader: warp w owns rows w*16 .. w*16+15 ----
    int t0 = blockIdx.x;
    auto issue_tile = [&](int t, int buf) {
        uint32_t xb = base + OFF_X + (uint32_t)buf * XB + (uint32_t)(warp * 16) * 528;
        const char* src = (const char*)(x + (size_t)(t * TM + warp * 16) * D_);
        #pragma unroll
        for (int i = 0; i < 16; i++) {
            int q = i * 32 + lane;                 // 0..511 -> 16 rows x 32 float4
            int row = q >> 5, c4 = q & 31;
            const char* g = ((t * TM + warp * 16 + row) < B) ? (src + (size_t)q * 16) : (const char*)x;
            cpasync16(xb + (uint32_t)row * 528 + (uint32_t)c4 * 16, g);
        }
        asm volatile("cp.async.commit_group;" ::: "memory");
    };
    if (t0 < NT) issue_tile(t0, 0);

    float* sb  = (float*)(sm + OFF_SB);
    float* sg  = (float*)(sm + OFF_SG);
    float* sbe = (float*)(sm + OFF_SBE);
    float* scb = (float*)(sm + OFF_SCB);
    float* gk  = (float*)(sm + OFF_GK);
    float* bbk = (float*)(sm + OFF_BBK);
    float* bdk = (float*)(sm + OFF_BDK);
    float* sci = (float*)(sm + OFF_SCI);

    // ---- stage W (scaled x256, fp16 hi/lo split) as [n][k], stride 272 B ----
    #pragma unroll 1
    for (int q2 = tid; q2 < 8192; q2 += NTH) {
        int n = q2 >> 6, kp = q2 & 63;
        float2 v = *(const float2*)&W[(size_t)n * 128 + 2 * kp];
        v.x *= WSCALE; v.y *= WSCALE;
        uint32_t hi, lo; split2(v.x, v.y, hi, lo);
        uint32_t off = (uint32_t)n * 272 + (uint32_t)kp * 4;
        *(uint32_t*)(sm + OFF_W1 + off) = hi;
        *(uint32_t*)(sm + OFF_W2 + off) = lo;
    }
    if (tid < 128) { sb[tid] = bias[tid]; sg[tid] = gamma[tid]; sbe[tid] = beta[tid]; }
    #pragma unroll 1
    for (int i = tid; i < 1024; i += NTH) { int k = i >> 7, j = i & 127; scb[k * 132 + j] = cb[i]; }
    __syncthreads();

    // ---- ck'' = W^T (gamma o c_k) appended as B-rows 128..135 ----
    if (tid < 128) {
        int d = tid;
        float a8[8] = {0, 0, 0, 0, 0, 0, 0, 0};
        #pragma unroll 4
        for (int j = 0; j < 128; j++) {
            float tj = W[(size_t)j * 128 + d] * sg[j];
            #pragma unroll
            for (int k = 0; k < 8; k++) a8[k] = fmaf(tj, scb[k * 132 + j], a8[k]);
        }
        #pragma unroll
        for (int k = 0; k < 8; k++) {
            float vs = a8[k] * WSCALE;
            __half h1 = __float2half_rn(vs);
            __half h2 = __float2half_rn(vs - __half2float(h1));
            uint32_t off = (uint32_t)(128 + k) * 272 + (uint32_t)d * 2;
            *(__half*)(sm + OFF_W1 + off) = h1;
            *(__half*)(sm + OFF_W2 + off) = h2;
        }
    }
    if (tid < 8) {
        int k = tid; float g = 0, bb = 0, bd = 0, s2 = 0;
        for (int j = 0; j < 128; j++) {
            float c = scb[k * 132 + j], gj = sg[j];
            g  = fmaf(gj, c, g);
            bb = fmaf(sbe[j], c, bb);
            bd = fmaf(sb[j] * gj, c, bd);
            s2 = fmaf(c, c, s2);
        }
        gk[k] = g; bbk[k] = bb; bdk[k] = bd;
        sci[k] = 1.0f / fmaxf(sqrtf(s2), 1e-12f);
    }
    __syncthreads();
    // After this point: W/params smem is read-only, x buffers are warp-private.
    // NO block barriers in the main loop — warps run decoupled pipelines.

    const int g4 = lane >> 2, c4l = lane & 3;
    const uint32_t boff = (uint32_t)(lane & 7) * 272 + (uint32_t)(lane >> 3) * 16;

    int s = 0;
    for (int t = t0; t < NT; t += grid) {
        int tn = t + grid;
        if (tn < NT) {
            issue_tile(tn, s ^ 1);
            asm volatile("cp.async.wait_group 1;" ::: "memory");
        } else {
            asm volatile("cp.async.wait_group 0;" ::: "memory");
        }
        __syncwarp();

        // ---- MMA: warp's 16 rows x N=136 (17 n-tiles), K=128, 3 passes ----
        float4 acc[17];
        #pragma unroll
        for (int j = 0; j < 17; j++) acc[j] = make_float4(0.f, 0.f, 0.f, 0.f);

        const char* smx = sm + OFF_X + (size_t)s * XB;
        const uint32_t xrow = (uint32_t)(warp * 16 + g4) * 528;

        #pragma unroll 1
        for (int kp = 0; kp < 4; kp++) {
            uint32_t ah[2][4], al[2][4];
            #pragma unroll
            for (int kk = 0; kk < 2; kk++) {
                const char* p = smx + xrow + (uint32_t)((kp * 2 + kk) * 16 + 2 * c4l) * 4;
                float2 v0 = *(const float2*)(p);
                float2 v1 = *(const float2*)(p + 8 * 528);
                float2 v2 = *(const float2*)(p + 32);
                float2 v3 = *(const float2*)(p + 8 * 528 + 32);
                split2(v0.x * XSCALE, v0.y * XSCALE, ah[kk][0], al[kk][0]);
                split2(v1.x * XSCALE, v1.y * XSCALE, ah[kk][1], al[kk][1]);
                split2(v2.x * XSCALE, v2.y * XSCALE, ah[kk][2], al[kk][2]);
                split2(v3.x * XSCALE, v3.y * XSCALE, ah[kk][3], al[kk][3]);
            }
            uint32_t wk = base + boff + (uint32_t)kp * 64;
            #pragma unroll
            for (int j = 0; j < 17; j++) {
                uint32_t waddr = wk + (uint32_t)j * (8 * 272);
                uint32_t bh[4], bl[4];
                ldmx4(bh, waddr + OFF_W1);
                ldmx4(bl, waddr + OFF_W2);
                mma16816(acc[j], ah[0], bh[0], bh[1]);
                mma16816(acc[j], ah[0], bl[0], bl[1]);
                mma16816(acc[j], al[0], bh[0], bh[1]);
                mma16816(acc[j], ah[1], bh[2], bh[3]);
                mma16816(acc[j], ah[1], bl[2], bl[3]);
                mma16816(acc[j], al[1], bh[2], bh[3]);
            }
        }

        // ---- epilogue: 2 rows per thread (hf = 0/1) ----
        int bi2[2];
        #pragma unroll 1
        for (int hf = 0; hf < 2; hf++) {
            int rowloc = warp * 16 + hf * 8 + g4;
            int grow = t * TM + rowloc;

            float s1 = 0.f, s2 = 0.f;
            #pragma unroll
            for (int j = 0; j < 16; j++) {
                float a0 = hf ? acc[j].z : acc[j].x;
                float a1 = hf ? acc[j].w : acc[j].y;
                float2 bb = *(const float2*)(sm + OFF_SB + (8 * j + 2 * c4l) * 4);
                float h0 = fmaf(a0, INV_SC, bb.x);
                float h1 = fmaf(a1, INV_SC, bb.y);
                s1 += h0 + h1;
                s2 = fmaf(h0, h0, fmaf(h1, h1, s2));
            }
            s1 += __shfl_xor_sync(0xffffffffu, s1, 1);
            s1 += __shfl_xor_sync(0xffffffffu, s1, 2);
            s2 += __shfl_xor_sync(0xffffffffu, s2, 1);
            s2 += __shfl_xor_sync(0xffffffffu, s2, 2);
            float mu = s1 * 0.0078125f;
            float var = s2 * 0.0078125f - mu * mu;
            float rstd = rsqrtf(var + 1e-5f);

            float q2 = 0.f;
            #pragma unroll
            for (int j = 0; j < 16; j++) {
                float a0 = hf ? acc[j].z : acc[j].x;
                float a1 = hf ? acc[j].w : acc[j].y;
                float2 bb = *(const float2*)(sm + OFF_SB + (8 * j + 2 * c4l) * 4);
                float2 gg = *(const float2*)(sm + OFF_SG + (8 * j + 2 * c4l) * 4);
                float2 be = *(const float2*)(sm + OFF_SBE + (8 * j + 2 * c4l) * 4);
                float h0 = fmaf(a0, INV_SC, bb.x);
                float h1 = fmaf(a1, INV_SC, bb.y);
                float hn0 = fmaf((h0 - mu) * rstd, gg.x, be.x);
                float hn1 = fmaf((h1 - mu) * rstd, gg.y, be.y);
                q2 = fmaf(hn0, hn0, fmaf(hn1, hn1, q2));
            }
            q2 += __shfl_xor_sync(0xffffffffu, q2, 1);
            q2 += __shfl_xor_sync(0xffffffffu, q2, 2);
            float invn = 1.0f / fmaxf(sqrtf(q2), 1e-12f);

            float k0 = hf ? acc[16].z : acc[16].x;
            float k1 = hf ? acc[16].w : acc[16].y;
            float H0 = fmaf(k0, INV_SC, bdk[2 * c4l]);
            float H1 = fmaf(k1, INV_SC, bdk[2 * c4l + 1]);
            float l0 = fmaf(rstd, H0 - mu * gk[2 * c4l],     bbk[2 * c4l])     * invn * sci[2 * c4l];
            float l1 = fmaf(rstd, H1 - mu * gk[2 * c4l + 1], bbk[2 * c4l + 1]) * invn * sci[2 * c4l + 1];

            float lg[8];
            #pragma unroll
            for (int kk = 0; kk < 8; kk++) {
                int src = (lane & ~3) | (kk >> 1);
                lg[kk] = __shfl_sync(0xffffffffu, (kk & 1) ? l1 : l0, src);
            }
            float mx = lg[0]; int bi = 0;
            #pragma unroll
            for (int kk = 1; kk < 8; kk++) if (lg[kk] > mx) { mx = lg[kk]; bi = kk; }
            bi2[hf] = bi;
            float e[8], ss = 0.f;
            #pragma unroll
            for (int kk = 0; kk < 8; kk++) { e[kk] = __expf(lg[kk] - mx); ss += e[kk]; }
            float rs = 1.0f / ss;

            if (c4l == 0 && grow < B) {
                o_idx[grow] = (float)bi;
                *(float4*)&o_soft[(size_t)grow * 8]     = make_float4(e[0]*rs, e[1]*rs, e[2]*rs, e[3]*rs);
                *(float4*)&o_soft[(size_t)grow * 8 + 4] = make_float4(e[4]*rs, e[5]*rs, e[6]*rs, e[7]*rs);
                *(float4*)&o_log [(size_t)grow * 8]     = make_float4(lg[0], lg[1], lg[2], lg[3]);
                *(float4*)&o_log [(size_t)grow * 8 + 4] = make_float4(lg[4], lg[5], lg[6], lg[7]);
            }
        }

        // ---- embedding write: warp-local, coalesced 512B per row ----
        #pragma unroll 1
        for (int r = 0; r < 16; r++) {
            int bsrc = __shfl_sync(0xffffffffu, (r >= 8) ? bi2[1] : bi2[0], (r & 7) * 4);
            int grow = t * TM + warp * 16 + r;
            if (grow < B) {
                float4 v = *(const float4*)(sm + OFF_SCB + ((size_t)bsrc * 132 + lane * 4) * 4);
                *(float4*)&o_emb[(size_t)grow * 128 + lane * 4] = v;
            }
        }
        s ^= 1;
    }
}

extern "C" void kernel_launch(void* const* d_in, const int* in_sizes, int n_in,
                              void* d_out, int out_size) {
    const float* x  = (const float*)d_in[0];
    const float* W  = (const float*)d_in[1];
    const float* b  = (const float*)d_in[2];
    const float* g  = (const float*)d_in[3];
    const float* be = (const float*)d_in[4];
    const float* cb = (const float*)d_in[5];

    int B = in_sizes[0] / D_;
    float* out    = (float*)d_out;
    float* o_idx  = out;
    float* o_soft = out + (size_t)B;
    float* o_emb  = o_soft + (size_t)B * 8;
    float* o_log  = o_emb + (size_t)B * 128;

    int NT = (B + TM - 1) / TM;
    int sms = 148;
    cudaDeviceGetAttribute(&sms, cudaDevAttrMultiProcessorCount, 0);
    int grid = (NT < sms) ? NT : sms;

    cudaFuncSetAttribute(l1q_mma, cudaFuncAttributeMaxDynamicSharedMemorySize, SMEM_TOTAL);
    l1q_mma<<<grid, NTH, SMEM_TOTAL>>>(x, W, b, g, be, cb,
                                       o_idx, o_soft, o_emb, o_log, B, NT, grid);
}

// round 11
// speedup vs baseline: 3.1960x; 1.1193x over previous
#include <cuda_runtime.h>
#include <cuda_fp16.h>
#include <cstdint>

#define D_ 128
#define TM 128
#define NTH 256
#define XSCALE 1024.0f
#define WSCALE 256.0f
#define INV_SC 3.814697265625e-06f   // 2^-18

// smem layout (bytes) — x never touches smem
#define WB 36992                      // 136 n-rows * 272 B
#define OFF_W1 0
#define OFF_W2 WB
#define OFF_SB  (2*WB)                // 73984
#define OFF_SG  (OFF_SB + 512)
#define OFF_SBE (OFF_SG + 512)
#define OFF_GBE (OFF_SBE + 512)       // 64 float4: {g[2i],g[2i+1],be[2i],be[2i+1]}
#define OFF_SCB (OFF_GBE + 1024)      // 8 * 132 * 4 = 4224
#define OFF_GK  (OFF_SCB + 4224)
#define OFF_BBK (OFF_GK + 32)
#define OFF_BDK (OFF_BBK + 32)
#define OFF_SCI (OFF_BDK + 32)
#define SMEM_TOTAL (OFF_SCI + 32)

__device__ __forceinline__ uint32_t s2u(const void* p) {
    uint32_t a;
    asm("{ .reg .u64 t; cvta.to.shared.u64 t, %1; cvt.u32.u64 %0, t; }" : "=r"(a) : "l"(p));
    return a;
}
__device__ __forceinline__ uint32_t f2h2(float lo, float hi) {
    uint32_t d;
    asm("cvt.rn.f16x2.f32 %0, %1, %2;" : "=r"(d) : "f"(hi), "f"(lo));
    return d;
}
__device__ __forceinline__ float2 h2f2(uint32_t h) {
    float2 r;
    asm("{ .reg .b16 l, hh; mov.b32 {l, hh}, %2; cvt.f32.f16 %0, l; cvt.f32.f16 %1, hh; }"
        : "=f"(r.x), "=f"(r.y) : "r"(h));
    return r;
}
__device__ __forceinline__ void split2(float a, float b, uint32_t& hi, uint32_t& lo) {
    hi = f2h2(a, b);
    float2 f = h2f2(hi);
    lo = f2h2(a - f.x, b - f.y);
}
__device__ __forceinline__ void ldmx4(uint32_t* r, uint32_t addr) {
    asm volatile("ldmatrix.sync.aligned.m8n8.x4.shared.b16 {%0,%1,%2,%3}, [%4];"
                 : "=r"(r[0]), "=r"(r[1]), "=r"(r[2]), "=r"(r[3]) : "r"(addr));
}
__device__ __forceinline__ void mma16816(float4& c, const uint32_t* a, uint32_t b0, uint32_t b1) {
    asm volatile("mma.sync.aligned.m16n8k16.row.col.f32.f16.f16.f32 "
                 "{%0,%1,%2,%3},{%4,%5,%6,%7},{%8,%9},{%0,%1,%2,%3};"
                 : "+f"(c.x), "+f"(c.y), "+f"(c.z), "+f"(c.w)
                 : "r"(a[0]), "r"(a[1]), "r"(a[2]), "r"(a[3]), "r"(b0), "r"(b1));
}

__global__ void __launch_bounds__(NTH, 1)
l1q_mma(const float* __restrict__ x, const float* __restrict__ W,
        const float* __restrict__ bias, const float* __restrict__ gamma,
        const float* __restrict__ beta, const float* __restrict__ cb,
        float* __restrict__ o_idx, float* __restrict__ o_soft,
        float* __restrict__ o_emb, float* __restrict__ o_log,
        int B, int NT, int grid)
{
    extern __shared__ char sm[];
    const uint32_t base = s2u(sm);
    const int tid = threadIdx.x;
    const int lane = tid & 31;
    const int warp = tid >> 5;

    float* sb  = (float*)(sm + OFF_SB);
    float* sg  = (float*)(sm + OFF_SG);
    float* sbe = (float*)(sm + OFF_SBE);
    float* scb = (float*)(sm + OFF_SCB);
    float* gk  = (float*)(sm + OFF_GK);
    float* bbk = (float*)(sm + OFF_BBK);
    float* bdk = (float*)(sm + OFF_BDK);
    float* sci = (float*)(sm + OFF_SCI);

    // ---- stage W (scaled x256, fp16 hi/lo split) as [n][k], stride 272 B ----
    #pragma unroll 1
    for (int q2 = tid; q2 < 8192; q2 += NTH) {
        int n = q2 >> 6, kp = q2 & 63;
        float2 v = *(const float2*)&W[(size_t)n * 128 + 2 * kp];
        v.x *= WSCALE; v.y *= WSCALE;
        uint32_t hi, lo; split2(v.x, v.y, hi, lo);
        uint32_t off = (uint32_t)n * 272 + (uint32_t)kp * 4;
        *(uint32_t*)(sm + OFF_W1 + off) = hi;
        *(uint32_t*)(sm + OFF_W2 + off) = lo;
    }
    if (tid < 128) { sb[tid] = bias[tid]; sg[tid] = gamma[tid]; sbe[tid] = beta[tid]; }
    #pragma unroll 1
    for (int i = tid; i < 1024; i += NTH) { int k = i >> 7, j = i & 127; scb[k * 132 + j] = cb[i]; }
    __syncthreads();
    if (tid < 64) {
        float4 gb;
        gb.x = sg[2 * tid]; gb.y = sg[2 * tid + 1];
        gb.z = sbe[2 * tid]; gb.w = sbe[2 * tid + 1];
        *(float4*)(sm + OFF_GBE + tid * 16) = gb;
    }

    // ---- ck'' = W^T (gamma o c_k) appended as B-rows 128..135 ----
    if (tid < 128) {
        int d = tid;
        float a8[8] = {0, 0, 0, 0, 0, 0, 0, 0};
        #pragma unroll 4
        for (int j = 0; j < 128; j++) {
            float tj = W[(size_t)j * 128 + d] * sg[j];
            #pragma unroll
            for (int k = 0; k < 8; k++) a8[k] = fmaf(tj, scb[k * 132 + j], a8[k]);
        }
        #pragma unroll
        for (int k = 0; k < 8; k++) {
            float vs = a8[k] * WSCALE;
            __half h1 = __float2half_rn(vs);
            __half h2 = __float2half_rn(vs - __half2float(h1));
            uint32_t off = (uint32_t)(128 + k) * 272 + (uint32_t)d * 2;
            *(__half*)(sm + OFF_W1 + off) = h1;
            *(__half*)(sm + OFF_W2 + off) = h2;
        }
    }
    if (tid < 8) {
        int k = tid; float g = 0, bb = 0, bd = 0, s2 = 0;
        for (int j = 0; j < 128; j++) {
            float c = scb[k * 132 + j], gj = sg[j];
            g  = fmaf(gj, c, g);
            bb = fmaf(sbe[j], c, bb);
            bd = fmaf(sb[j] * gj, c, bd);
            s2 = fmaf(c, c, s2);
        }
        gk[k] = g; bbk[k] = bb; bdk[k] = bd;
        sci[k] = 1.0f / fmaxf(sqrtf(s2), 1e-12f);
    }
    __syncthreads();
    // From here: smem is read-only; no block barriers in the main loop.

    const int g4 = lane >> 2, c4l = lane & 3;
    const uint32_t boff = (uint32_t)(lane & 7) * 272 + (uint32_t)(lane >> 3) * 16;
    const int rbase = warp * 16 + g4;

    // raw x fragment staging (global -> regs, 2-kp pipeline)
    float2 Pa[8], Pb[8];
    auto ldkp = [&](float2* R, const float* p0, const float* p1, int kp) {
        int b0 = kp * 32 + 2 * c4l;
        R[0] = *(const float2*)(p0 + b0);
        R[1] = *(const float2*)(p1 + b0);
        R[2] = *(const float2*)(p0 + b0 + 8);
        R[3] = *(const float2*)(p1 + b0 + 8);
        R[4] = *(const float2*)(p0 + b0 + 16);
        R[5] = *(const float2*)(p1 + b0 + 16);
        R[6] = *(const float2*)(p0 + b0 + 24);
        R[7] = *(const float2*)(p1 + b0 + 24);
    };
    auto rowptr = [&](int t_, int add) -> const float* {
        long r = (long)t_ * TM + rbase + add;
        if (r > (long)B - 1) r = B - 1;
        return x + (size_t)r * D_;
    };

    int t0 = blockIdx.x;
    const float* pr0 = rowptr(t0 < NT ? t0 : 0, 0);
    const float* pr1 = rowptr(t0 < NT ? t0 : 0, 8);
    if (t0 < NT) { ldkp(Pa, pr0, pr1, 0); ldkp(Pb, pr0, pr1, 1); }

    for (int t = t0; t < NT; t += grid) {
        int tn = t + grid;
        const float* nr0 = (tn < NT) ? rowptr(tn, 0) : pr0;
        const float* nr1 = (tn < NT) ? rowptr(tn, 8) : pr1;

        // ---- MMA: warp's 16 rows x N=136 (17 n-tiles), K=128, 3 passes ----
        float4 acc[17];
        #pragma unroll
        for (int j = 0; j < 17; j++) acc[j] = make_float4(0.f, 0.f, 0.f, 0.f);

        #pragma unroll
        for (int kp = 0; kp < 4; kp++) {
            float2* cur = (kp & 1) ? Pb : Pa;
            uint32_t ah[2][4], al[2][4];
            #pragma unroll
            for (int kk = 0; kk < 2; kk++)
                #pragma unroll
                for (int v = 0; v < 4; v++)
                    split2(cur[kk * 4 + v].x * XSCALE, cur[kk * 4 + v].y * XSCALE,
                           ah[kk][v], al[kk][v]);
            // prefetch: kp+2 of this tile, then kp0/kp1 of next tile
            if (kp == 0)      ldkp(Pa, pr0, pr1, 2);
            else if (kp == 1) ldkp(Pb, pr0, pr1, 3);
            else if (kp == 2) ldkp(Pa, nr0, nr1, 0);
            else              ldkp(Pb, nr0, nr1, 1);

            uint32_t wk = base + boff + (uint32_t)kp * 64;
            #pragma unroll
            for (int j = 0; j < 17; j++) {
                uint32_t waddr = wk + (uint32_t)j * (8 * 272);
                uint32_t bh[4], bl[4];
                ldmx4(bh, waddr + OFF_W1);
                ldmx4(bl, waddr + OFF_W2);
                mma16816(acc[j], ah[0], bh[0], bh[1]);
                mma16816(acc[j], ah[0], bl[0], bl[1]);
                mma16816(acc[j], al[0], bh[0], bh[1]);
                mma16816(acc[j], ah[1], bh[2], bh[3]);
                mma16816(acc[j], ah[1], bl[2], bl[3]);
                mma16816(acc[j], al[1], bh[2], bh[3]);
            }
        }
        pr0 = nr0; pr1 = nr1;

        // ---- fused epilogue: both half-rows together, h overwrites acc ----
        float s1a = 0.f, s2a = 0.f, s1b = 0.f, s2b = 0.f;
        #pragma unroll
        for (int j = 0; j < 16; j++) {
            float2 bb = *(const float2*)(sm + OFF_SB + (8 * j + 2 * c4l) * 4);
            float h0 = fmaf(acc[j].x, INV_SC, bb.x);
            float h1 = fmaf(acc[j].y, INV_SC, bb.y);
            float h2 = fmaf(acc[j].z, INV_SC, bb.x);
            float h3 = fmaf(acc[j].w, INV_SC, bb.y);
            acc[j] = make_float4(h0, h1, h2, h3);
            s1a += h0 + h1; s2a = fmaf(h0, h0, fmaf(h1, h1, s2a));
            s1b += h2 + h3; s2b = fmaf(h2, h2, fmaf(h3, h3, s2b));
        }
        s1a += __shfl_xor_sync(0xffffffffu, s1a, 1); s1a += __shfl_xor_sync(0xffffffffu, s1a, 2);
        s2a += __shfl_xor_sync(0xffffffffu, s2a, 1); s2a += __shfl_xor_sync(0xffffffffu, s2a, 2);
        s1b += __shfl_xor_sync(0xffffffffu, s1b, 1); s1b += __shfl_xor_sync(0xffffffffu, s1b, 2);
        s2b += __shfl_xor_sync(0xffffffffu, s2b, 1); s2b += __shfl_xor_sync(0xffffffffu, s2b, 2);
        float mua = s1a * 0.0078125f, mub = s1b * 0.0078125f;
        float rstda = rsqrtf(s2a * 0.0078125f - mua * mua + 1e-5f);
        float rstdb = rsqrtf(s2b * 0.0078125f - mub * mub + 1e-5f);

        float q2a = 0.f, q2b = 0.f;
        #pragma unroll
        for (int j = 0; j < 16; j++) {
            float4 gb = *(const float4*)(sm + OFF_GBE + (4 * j + c4l) * 16);
            float hn0 = fmaf((acc[j].x - mua) * rstda, gb.x, gb.z);
            float hn1 = fmaf((acc[j].y - mua) * rstda, gb.y, gb.w);
            float hn2 = fmaf((acc[j].z - mub) * rstdb, gb.x, gb.z);
            float hn3 = fmaf((acc[j].w - mub) * rstdb, gb.y, gb.w);
            q2a = fmaf(hn0, hn0, fmaf(hn1, hn1, q2a));
            q2b = fmaf(hn2, hn2, fmaf(hn3, hn3, q2b));
        }
        q2a += __shfl_xor_sync(0xffffffffu, q2a, 1); q2a += __shfl_xor_sync(0xffffffffu, q2a, 2);
        q2b += __shfl_xor_sync(0xffffffffu, q2b, 1); q2b += __shfl_xor_sync(0xffffffffu, q2b, 2);
        float invna = 1.0f / fmaxf(sqrtf(q2a), 1e-12f);
        float invnb = 1.0f / fmaxf(sqrtf(q2b), 1e-12f);

        float bd0 = bdk[2 * c4l], bd1 = bdk[2 * c4l + 1];
        float gk0 = gk[2 * c4l],  gk1 = gk[2 * c4l + 1];
        float bk0 = bbk[2 * c4l], bk1 = bbk[2 * c4l + 1];
        float sc0 = sci[2 * c4l], sc1 = sci[2 * c4l + 1];
        float l0a = fmaf(rstda, fmaf(acc[16].x, INV_SC, bd0) - mua * gk0, bk0) * invna * sc0;
        float l1a = fmaf(rstda, fmaf(acc[16].y, INV_SC, bd1) - mua * gk1, bk1) * invna * sc1;
        float l0b = fmaf(rstdb, fmaf(acc[16].z, INV_SC, bd0) - mub * gk0, bk0) * invnb * sc0;
        float l1b = fmaf(rstdb, fmaf(acc[16].w, INV_SC, bd1) - mub * gk1, bk1) * invnb * sc1;

        int bi2[2];
        #pragma unroll 1
        for (int hf = 0; hf < 2; hf++) {
            float l0 = hf ? l0b : l0a, l1 = hf ? l1b : l1a;
            int grow = t * TM + warp * 16 + hf * 8 + g4;

            float lg[8];
            #pragma unroll
            for (int kk = 0; kk < 8; kk++) {
                int src = (lane & ~3) | (kk >> 1);
                lg[kk] = __shfl_sync(0xffffffffu, (kk & 1) ? l1 : l0, src);
            }
            float mx = lg[0]; int bi = 0;
            #pragma unroll
            for (int kk = 1; kk < 8; kk++) if (lg[kk] > mx) { mx = lg[kk]; bi = kk; }
            bi2[hf] = bi;
            float e[8], ss = 0.f;
            #pragma unroll
            for (int kk = 0; kk < 8; kk++) { e[kk] = __expf(lg[kk] - mx); ss += e[kk]; }
            float rs = 1.0f / ss;

            if (c4l == 0 && grow < B) {
                o_idx[grow] = (float)bi;
                *(float4*)&o_soft[(size_t)grow * 8]     = make_float4(e[0]*rs, e[1]*rs, e[2]*rs, e[3]*rs);
                *(float4*)&o_soft[(size_t)grow * 8 + 4] = make_float4(e[4]*rs, e[5]*rs, e[6]*rs, e[7]*rs);
                *(float4*)&o_log [(size_t)grow * 8]     = make_float4(lg[0], lg[1], lg[2], lg[3]);
                *(float4*)&o_log [(size_t)grow * 8 + 4] = make_float4(lg[4], lg[5], lg[6], lg[7]);
            }
        }

        // ---- embedding write: warp-local, coalesced 512 B per row ----
        #pragma unroll 1
        for (int r = 0; r < 16; r++) {
            int bsrc = __shfl_sync(0xffffffffu, (r >= 8) ? bi2[1] : bi2[0], (r & 7) * 4);
            int grow = t * TM + warp * 16 + r;
            if (grow < B) {
                float4 v = *(const float4*)(sm + OFF_SCB + ((size_t)bsrc * 132 + lane * 4) * 4);
                *(float4*)&o_emb[(size_t)grow * 128 + lane * 4] = v;
            }
        }
    }
}

extern "C" void kernel_launch(void* const* d_in, const int* in_sizes, int n_in,
                              void* d_out, int out_size) {
    const float* x  = (const float*)d_in[0];
    const float* W  = (const float*)d_in[1];
    const float* b  = (const float*)d_in[2];
    const float* g  = (const float*)d_in[3];
    const float* be = (const float*)d_in[4];
    const float* cb = (const float*)d_in[5];

    int B = in_sizes[0] / D_;
    float* out    = (float*)d_out;
    float* o_idx  = out;
    float* o_soft = out + (size_t)B;
    float* o_emb  = o_soft + (size_t)B * 8;
    float* o_log  = o_emb + (size_t)B * 128;

    int NT = (B + TM - 1) / TM;
    int sms = 148;
    cudaDeviceGetAttribute(&sms, cudaDevAttrMultiProcessorCount, 0);
    int grid = (NT < sms) ? NT : sms;

    cudaFuncSetAttribute(l1q_mma, cudaFuncAttributeMaxDynamicSharedMemorySize, SMEM_TOTAL);
    l1q_mma<<<grid, NTH, SMEM_TOTAL>>>(x, W, b, g, be, cb,
                                       o_idx, o_soft, o_emb, o_log, B, NT, grid);
}

// round 12
// speedup vs baseline: 3.3853x; 1.0592x over previous
#include <cuda_runtime.h>
#include <cuda_fp16.h>
#include <cstdint>

#define D_ 128
#define TM 192
#define NTH 384
#define XSCALE 1024.0f
#define WSCALE 256.0f
#define INV_SC 3.814697265625e-06f   // 2^-18

// smem layout (bytes) — x never touches smem
#define WB 36992                      // 136 n-rows * 272 B
#define OFF_W1 0
#define OFF_W2 WB
#define OFF_SB  (2*WB)                // 73984
#define OFF_SG  (OFF_SB + 512)
#define OFF_SBE (OFF_SG + 512)
#define OFF_GBE (OFF_SBE + 512)       // 64 float4: {g[2i],g[2i+1],be[2i],be[2i+1]}
#define OFF_SCB (OFF_GBE + 1024)      // 8 * 132 * 4 = 4224
#define OFF_GK  (OFF_SCB + 4224)
#define OFF_BBK (OFF_GK + 32)
#define OFF_BDK (OFF_BBK + 32)
#define OFF_SCI (OFF_BDK + 32)
#define SMEM_TOTAL (OFF_SCI + 32)

__device__ __forceinline__ uint32_t s2u(const void* p) {
    uint32_t a;
    asm("{ .reg .u64 t; cvta.to.shared.u64 t, %1; cvt.u32.u64 %0, t; }" : "=r"(a) : "l"(p));
    return a;
}
__device__ __forceinline__ uint32_t f2h2(float lo, float hi) {
    uint32_t d;
    asm("cvt.rn.f16x2.f32 %0, %1, %2;" : "=r"(d) : "f"(hi), "f"(lo));
    return d;
}
__device__ __forceinline__ float2 h2f2(uint32_t h) {
    float2 r;
    asm("{ .reg .b16 l, hh; mov.b32 {l, hh}, %2; cvt.f32.f16 %0, l; cvt.f32.f16 %1, hh; }"
        : "=f"(r.x), "=f"(r.y) : "r"(h));
    return r;
}
__device__ __forceinline__ void split2(float a, float b, uint32_t& hi, uint32_t& lo) {
    hi = f2h2(a, b);
    float2 f = h2f2(hi);
    lo = f2h2(a - f.x, b - f.y);
}
__device__ __forceinline__ void ldmx4(uint32_t* r, uint32_t addr) {
    asm volatile("ldmatrix.sync.aligned.m8n8.x4.shared.b16 {%0,%1,%2,%3}, [%4];"
                 : "=r"(r[0]), "=r"(r[1]), "=r"(r[2]), "=r"(r[3]) : "r"(addr));
}
__device__ __forceinline__ void mma16816(float4& c, const uint32_t* a, uint32_t b0, uint32_t b1) {
    asm volatile("mma.sync.aligned.m16n8k16.row.col.f32.f16.f16.f32 "
                 "{%0,%1,%2,%3},{%4,%5,%6,%7},{%8,%9},{%0,%1,%2,%3};"
                 : "+f"(c.x), "+f"(c.y), "+f"(c.z), "+f"(c.w)
                 : "r"(a[0]), "r"(a[1]), "r"(a[2]), "r"(a[3]), "r"(b0), "r"(b1));
}

__global__ void __launch_bounds__(NTH, 1)
l1q_mma(const float* __restrict__ x, const float* __restrict__ W,
        const float* __restrict__ bias, const float* __restrict__ gamma,
        const float* __restrict__ beta, const float* __restrict__ cb,
        float* __restrict__ o_idx, float* __restrict__ o_soft,
        float* __restrict__ o_emb, float* __restrict__ o_log,
        int B, int NT, int grid)
{
    extern __shared__ char sm[];
    const uint32_t base = s2u(sm);
    const int tid = threadIdx.x;
    const int lane = tid & 31;
    const int warp = tid >> 5;

    float* sb  = (float*)(sm + OFF_SB);
    float* sg  = (float*)(sm + OFF_SG);
    float* sbe = (float*)(sm + OFF_SBE);
    float* scb = (float*)(sm + OFF_SCB);
    float* gk  = (float*)(sm + OFF_GK);
    float* bbk = (float*)(sm + OFF_BBK);
    float* bdk = (float*)(sm + OFF_BDK);
    float* sci = (float*)(sm + OFF_SCI);

    // ---- stage W (scaled x256, fp16 hi/lo split) as [n][k], stride 272 B ----
    #pragma unroll 1
    for (int q2 = tid; q2 < 8192; q2 += NTH) {
        int n = q2 >> 6, kp = q2 & 63;
        float2 v = *(const float2*)&W[(size_t)n * 128 + 2 * kp];
        v.x *= WSCALE; v.y *= WSCALE;
        uint32_t hi, lo; split2(v.x, v.y, hi, lo);
        uint32_t off = (uint32_t)n * 272 + (uint32_t)kp * 4;
        *(uint32_t*)(sm + OFF_W1 + off) = hi;
        *(uint32_t*)(sm + OFF_W2 + off) = lo;
    }
    if (tid < 128) { sb[tid] = bias[tid]; sg[tid] = gamma[tid]; sbe[tid] = beta[tid]; }
    #pragma unroll 1
    for (int i = tid; i < 1024; i += NTH) { int k = i >> 7, j = i & 127; scb[k * 132 + j] = cb[i]; }
    __syncthreads();
    if (tid < 64) {
        float4 gb;
        gb.x = sg[2 * tid]; gb.y = sg[2 * tid + 1];
        gb.z = sbe[2 * tid]; gb.w = sbe[2 * tid + 1];
        *(float4*)(sm + OFF_GBE + tid * 16) = gb;
    }

    // ---- ck'' = W^T (gamma o c_k) appended as B-rows 128..135 ----
    if (tid < 128) {
        int d = tid;
        float a8[8] = {0, 0, 0, 0, 0, 0, 0, 0};
        #pragma unroll 4
        for (int j = 0; j < 128; j++) {
            float tj = W[(size_t)j * 128 + d] * sg[j];
            #pragma unroll
            for (int k = 0; k < 8; k++) a8[k] = fmaf(tj, scb[k * 132 + j], a8[k]);
        }
        #pragma unroll
        for (int k = 0; k < 8; k++) {
            float vs = a8[k] * WSCALE;
            __half h1 = __float2half_rn(vs);
            __half h2 = __float2half_rn(vs - __half2float(h1));
            uint32_t off = (uint32_t)(128 + k) * 272 + (uint32_t)d * 2;
            *(__half*)(sm + OFF_W1 + off) = h1;
            *(__half*)(sm + OFF_W2 + off) = h2;
        }
    }
    if (tid < 8) {
        int k = tid; float g = 0, bb = 0, bd = 0, s2 = 0;
        for (int j = 0; j < 128; j++) {
            float c = scb[k * 132 + j], gj = sg[j];
            g  = fmaf(gj, c, g);
            bb = fmaf(sbe[j], c, bb);
            bd = fmaf(sb[j] * gj, c, bd);
            s2 = fmaf(c, c, s2);
        }
        gk[k] = g; bbk[k] = bb; bdk[k] = bd;
        sci[k] = 1.0f / fmaxf(sqrtf(s2), 1e-12f);
    }
    __syncthreads();
    // From here: smem is read-only; no block barriers in the main loop.

    const int g4 = lane >> 2, c4l = lane & 3;
    const uint32_t boff = (uint32_t)(lane & 7) * 272 + (uint32_t)(lane >> 3) * 16;
    const int rbase = warp * 16 + g4;

    // raw x fragment staging (global -> regs, 2-kp pipeline)
    float2 Pa[8], Pb[8];
    auto ldkp = [&](float2* R, const float* p0, const float* p1, int kp) {
        int b0 = kp * 32 + 2 * c4l;
        R[0] = *(const float2*)(p0 + b0);
        R[1] = *(const float2*)(p1 + b0);
        R[2] = *(const float2*)(p0 + b0 + 8);
        R[3] = *(const float2*)(p1 + b0 + 8);
        R[4] = *(const float2*)(p0 + b0 + 16);
        R[5] = *(const float2*)(p1 + b0 + 16);
        R[6] = *(const float2*)(p0 + b0 + 24);
        R[7] = *(const float2*)(p1 + b0 + 24);
    };
    auto rowptr = [&](int t_, int add) -> const float* {
        long r = (long)t_ * TM + rbase + add;
        if (r > (long)B - 1) r = B - 1;
        return x + (size_t)r * D_;
    };

    int t0 = blockIdx.x;
    const float* pr0 = rowptr(t0 < NT ? t0 : 0, 0);
    const float* pr1 = rowptr(t0 < NT ? t0 : 0, 8);
    if (t0 < NT) { ldkp(Pa, pr0, pr1, 0); ldkp(Pb, pr0, pr1, 1); }

    for (int t = t0; t < NT; t += grid) {
        int tn = t + grid;
        const float* nr0 = (tn < NT) ? rowptr(tn, 0) : pr0;
        const float* nr1 = (tn < NT) ? rowptr(tn, 8) : pr1;

        // ---- MMA: warp's 16 rows x N=136 (17 n-tiles), K=128, 3 passes ----
        float4 acc[17];
        #pragma unroll
        for (int j = 0; j < 17; j++) acc[j] = make_float4(0.f, 0.f, 0.f, 0.f);

        #pragma unroll
        for (int kp = 0; kp < 4; kp++) {
            float2* cur = (kp & 1) ? Pb : Pa;
            uint32_t ah[2][4], al[2][4];
            #pragma unroll
            for (int kk = 0; kk < 2; kk++)
                #pragma unroll
                for (int v = 0; v < 4; v++)
                    split2(cur[kk * 4 + v].x * XSCALE, cur[kk * 4 + v].y * XSCALE,
                           ah[kk][v], al[kk][v]);
            // prefetch: kp+2 of this tile, then kp0/kp1 of next tile
            if (kp == 0)      ldkp(Pa, pr0, pr1, 2);
            else if (kp == 1) ldkp(Pb, pr0, pr1, 3);
            else if (kp == 2) ldkp(Pa, nr0, nr1, 0);
            else              ldkp(Pb, nr0, nr1, 1);

            uint32_t wk = base + boff + (uint32_t)kp * 64;
            // pair-interleaved j: dependency distance 2 on each acc register
            #pragma unroll
            for (int jp = 0; jp < 8; jp++) {
                int j0 = 2 * jp, j1 = 2 * jp + 1;
                uint32_t wa0 = wk + (uint32_t)j0 * (8 * 272);
                uint32_t wa1 = wk + (uint32_t)j1 * (8 * 272);
                uint32_t bh0[4], bl0[4], bh1[4], bl1[4];
                ldmx4(bh0, wa0 + OFF_W1);
                ldmx4(bh1, wa1 + OFF_W1);
                ldmx4(bl0, wa0 + OFF_W2);
                ldmx4(bl1, wa1 + OFF_W2);
                mma16816(acc[j0], ah[0], bh0[0], bh0[1]);
                mma16816(acc[j1], ah[0], bh1[0], bh1[1]);
                mma16816(acc[j0], ah[0], bl0[0], bl0[1]);
                mma16816(acc[j1], ah[0], bl1[0], bl1[1]);
                mma16816(acc[j0], al[0], bh0[0], bh0[1]);
                mma16816(acc[j1], al[0], bh1[0], bh1[1]);
                mma16816(acc[j0], ah[1], bh0[2], bh0[3]);
                mma16816(acc[j1], ah[1], bh1[2], bh1[3]);
                mma16816(acc[j0], ah[1], bl0[2], bl0[3]);
                mma16816(acc[j1], ah[1], bl1[2], bl1[3]);
                mma16816(acc[j0], al[1], bh0[2], bh0[3]);
                mma16816(acc[j1], al[1], bh1[2], bh1[3]);
            }
            {   // j = 16 singleton (logits columns)
                uint32_t wa = wk + (uint32_t)16 * (8 * 272);
                uint32_t bh[4], bl[4];
                ldmx4(bh, wa + OFF_W1);
                ldmx4(bl, wa + OFF_W2);
                mma16816(acc[16], ah[0], bh[0], bh[1]);
                mma16816(acc[16], ah[0], bl[0], bl[1]);
                mma16816(acc[16], al[0], bh[0], bh[1]);
                mma16816(acc[16], ah[1], bh[2], bh[3]);
                mma16816(acc[16], ah[1], bl[2], bl[3]);
                mma16816(acc[16], al[1], bh[2], bh[3]);
            }
        }
        pr0 = nr0; pr1 = nr1;

        // ---- fused epilogue: both half-rows together, h overwrites acc ----
        float s1a = 0.f, s2a = 0.f, s1b = 0.f, s2b = 0.f;
        #pragma unroll
        for (int j = 0; j < 16; j++) {
            float2 bb = *(const float2*)(sm + OFF_SB + (8 * j + 2 * c4l) * 4);
            float h0 = fmaf(acc[j].x, INV_SC, bb.x);
            float h1 = fmaf(acc[j].y, INV_SC, bb.y);
            float h2 = fmaf(acc[j].z, INV_SC, bb.x);
            float h3 = fmaf(acc[j].w, INV_SC, bb.y);
            acc[j] = make_float4(h0, h1, h2, h3);
            s1a += h0 + h1; s2a = fmaf(h0, h0, fmaf(h1, h1, s2a));
            s1b += h2 + h3; s2b = fmaf(h2, h2, fmaf(h3, h3, s2b));
        }
        s1a += __shfl_xor_sync(0xffffffffu, s1a, 1); s1a += __shfl_xor_sync(0xffffffffu, s1a, 2);
        s2a += __shfl_xor_sync(0xffffffffu, s2a, 1); s2a += __shfl_xor_sync(0xffffffffu, s2a, 2);
        s1b += __shfl_xor_sync(0xffffffffu, s1b, 1); s1b += __shfl_xor_sync(0xffffffffu, s1b, 2);
        s2b += __shfl_xor_sync(0xffffffffu, s2b, 1); s2b += __shfl_xor_sync(0xffffffffu, s2b, 2);
        float mua = s1a * 0.0078125f, mub = s1b * 0.0078125f;
        float rstda = rsqrtf(s2a * 0.0078125f - mua * mua + 1e-5f);
        float rstdb = rsqrtf(s2b * 0.0078125f - mub * mub + 1e-5f);

        float q2a = 0.f, q2b = 0.f;
        #pragma unroll
        for (int j = 0; j < 16; j++) {
            float4 gb = *(const float4*)(sm + OFF_GBE + (4 * j + c4l) * 16);
            float hn0 = fmaf((acc[j].x - mua) * rstda, gb.x, gb.z);
            float hn1 = fmaf((acc[j].y - mua) * rstda, gb.y, gb.w);
            float hn2 = fmaf((acc[j].z - mub) * rstdb, gb.x, gb.z);
            float hn3 = fmaf((acc[j].w - mub) * rstdb, gb.y, gb.w);
            q2a = fmaf(hn0, hn0, fmaf(hn1, hn1, q2a));
            q2b = fmaf(hn2, hn2, fmaf(hn3, hn3, q2b));
        }
        q2a += __shfl_xor_sync(0xffffffffu, q2a, 1); q2a += __shfl_xor_sync(0xffffffffu, q2a, 2);
        q2b += __shfl_xor_sync(0xffffffffu, q2b, 1); q2b += __shfl_xor_sync(0xffffffffu, q2b, 2);
        float invna = 1.0f / fmaxf(sqrtf(q2a), 1e-12f);
        float invnb = 1.0f / fmaxf(sqrtf(q2b), 1e-12f);

        float bd0 = bdk[2 * c4l], bd1 = bdk[2 * c4l + 1];
        float gk0 = gk[2 * c4l],  gk1 = gk[2 * c4l + 1];
        float bk0 = bbk[2 * c4l], bk1 = bbk[2 * c4l + 1];
        float sc0 = sci[2 * c4l], sc1 = sci[2 * c4l + 1];
        float l0a = fmaf(rstda, fmaf(acc[16].x, INV_SC, bd0) - mua * gk0, bk0) * invna * sc0;
        float l1a = fmaf(rstda, fmaf(acc[16].y, INV_SC, bd1) - mua * gk1, bk1) * invna * sc1;
        float l0b = fmaf(rstdb, fmaf(acc[16].z, INV_SC, bd0) - mub * gk0, bk0) * invnb * sc0;
        float l1b = fmaf(rstdb, fmaf(acc[16].w, INV_SC, bd1) - mub * gk1, bk1) * invnb * sc1;

        int bi2[2];
        #pragma unroll 1
        for (int hf = 0; hf < 2; hf++) {
            float l0 = hf ? l0b : l0a, l1 = hf ? l1b : l1a;
            int grow = t * TM + warp * 16 + hf * 8 + g4;

            float lg[8];
            #pragma unroll
            for (int kk = 0; kk < 8; kk++) {
                int src = (lane & ~3) | (kk >> 1);
                lg[kk] = __shfl_sync(0xffffffffu, (kk & 1) ? l1 : l0, src);
            }
            float mx = lg[0]; int bi = 0;
            #pragma unroll
            for (int kk = 1; kk < 8; kk++) if (lg[kk] > mx) { mx = lg[kk]; bi = kk; }
            bi2[hf] = bi;
            float e[8], ss = 0.f;
            #pragma unroll
            for (int kk = 0; kk < 8; kk++) { e[kk] = __expf(lg[kk] - mx); ss += e[kk]; }
            float rs = 1.0f / ss;

            if (c4l == 0 && grow < B) {
                o_idx[grow] = (float)bi;
                *(float4*)&o_soft[(size_t)grow * 8]     = make_float4(e[0]*rs, e[1]*rs, e[2]*rs, e[3]*rs);
                *(float4*)&o_soft[(size_t)grow * 8 + 4] = make_float4(e[4]*rs, e[5]*rs, e[6]*rs, e[7]*rs);
                *(float4*)&o_log [(size_t)grow * 8]     = make_float4(lg[0], lg[1], lg[2], lg[3]);
                *(float4*)&o_log [(size_t)grow * 8 + 4] = make_float4(lg[4], lg[5], lg[6], lg[7]);
            }
        }

        // ---- embedding write: warp-local, coalesced 512 B per row ----
        #pragma unroll 1
        for (int r = 0; r < 16; r++) {
            int bsrc = __shfl_sync(0xffffffffu, (r >= 8) ? bi2[1] : bi2[0], (r & 7) * 4);
            int grow = t * TM + warp * 16 + r;
            if (grow < B) {
                float4 v = *(const float4*)(sm + OFF_SCB + ((size_t)bsrc * 132 + lane * 4) * 4);
                *(float4*)&o_emb[(size_t)grow * 128 + lane * 4] = v;
            }
        }
    }
}

extern "C" void kernel_launch(void* const* d_in, const int* in_sizes, int n_in,
                              void* d_out, int out_size) {
    const float* x  = (const float*)d_in[0];
    const float* W  = (const float*)d_in[1];
    const float* b  = (const float*)d_in[2];
    const float* g  = (const float*)d_in[3];
    const float* be = (const float*)d_in[4];
    const float* cb = (const float*)d_in[5];

    int B = in_sizes[0] / D_;
    float* out    = (float*)d_out;
    float* o_idx  = out;
    float* o_soft = out + (size_t)B;
    float* o_emb  = o_soft + (size_t)B * 8;
    float* o_log  = o_emb + (size_t)B * 128;

    int NT = (B + TM - 1) / TM;
    int sms = 148;
    cudaDeviceGetAttribute(&sms, cudaDevAttrMultiProcessorCount, 0);
    int grid = (NT < sms) ? NT : sms;

    cudaFuncSetAttribute(l1q_mma, cudaFuncAttributeMaxDynamicSharedMemorySize, SMEM_TOTAL);
    l1q_mma<<<grid, NTH, SMEM_TOTAL>>>(x, W, b, g, be, cb,
                                       o_idx, o_soft, o_emb, o_log, B, NT, grid);
}